// round 1
// baseline (speedup 1.0000x reference)
#include <cuda_runtime.h>
#include <math.h>

// ---------------------------------------------------------------------------
// EViT block: LN1 -> QKV GEMM -> fused attention -> proj GEMM (+bias+res)
//  -> token top-k / merge -> LN2 -> FC1 (+bias+GELU) -> FC2 (+bias+res)
// All fp32. Scratch lives in __device__ globals (no allocation in launch).
// ---------------------------------------------------------------------------

#define BBATCH 128
#define SEQ    197
#define CHN    768
#define NHEAD  12
#define HDIM   64
#define CH3    2304
#define HID    3072
#define LEFT   138     // ceil(0.7 * 196)
#define NCOMP  58      // 196 - 138
#define SEQ2   139     // 1 + LEFT
#define NM1    196

// ---- scratch ----
__device__ __align__(16) float g_xn  [BBATCH*SEQ*CHN];
__device__ __align__(16) float g_qkv [BBATCH*SEQ*CH3];
__device__ __align__(16) float g_ao  [BBATCH*SEQ*CHN];
__device__ __align__(16) float g_x1  [BBATCH*SEQ*CHN];
__device__ __align__(16) float g_clsh[BBATCH*NHEAD*NM1];
__device__ __align__(16) float g_cls [BBATCH*NM1];
__device__ int   g_idx [BBATCH*LEFT];
__device__ int   g_cmp [BBATCH*NCOMP];
__device__ float g_xon [BBATCH*LEFT];
__device__ int   g_node[BBATCH*NCOMP];
__device__ __align__(16) float g_xcat[BBATCH*SEQ2*CHN];
__device__ __align__(16) float g_xn2 [BBATCH*SEQ2*CHN];
__device__ __align__(16) float g_hmid[BBATCH*SEQ2*HID];

// ---------------------------------------------------------------------------
// block-wide sum reduce (256 threads)
// ---------------------------------------------------------------------------
__device__ __forceinline__ float block_sum(float v, float* red) {
    int t = threadIdx.x;
    #pragma unroll
    for (int o = 16; o; o >>= 1) v += __shfl_xor_sync(0xffffffffu, v, o);
    if ((t & 31) == 0) red[t >> 5] = v;
    __syncthreads();
    float z = 0.f;
    if (t < 32) {
        z = (t < 8) ? red[t] : 0.f;
        #pragma unroll
        for (int o = 4; o; o >>= 1) z += __shfl_xor_sync(0xffffffffu, z, o);
        if (t == 0) red[0] = z;
    }
    __syncthreads();
    float r = red[0];
    __syncthreads();
    return r;
}

// ---------------------------------------------------------------------------
// LayerNorm over last dim (768); one block per row, 256 threads, 3 elems/thr
// ---------------------------------------------------------------------------
__global__ void ln_kernel(const float* __restrict__ x, const float* __restrict__ w,
                          const float* __restrict__ b, float* __restrict__ y) {
    __shared__ float red[32];
    int row = blockIdx.x;
    const float* xr = x + (size_t)row * CHN;
    float* yr = y + (size_t)row * CHN;
    int t = threadIdx.x;
    float v0 = xr[t], v1 = xr[t + 256], v2 = xr[t + 512];
    float mean = block_sum(v0 + v1 + v2, red) * (1.f / CHN);
    float d0 = v0 - mean, d1 = v1 - mean, d2 = v2 - mean;
    float var = block_sum(d0*d0 + d1*d1 + d2*d2, red) * (1.f / CHN);
    float inv = rsqrtf(var + 1e-5f);
    yr[t]       = d0 * inv * w[t]       + b[t];
    yr[t + 256] = d1 * inv * w[t + 256] + b[t + 256];
    yr[t + 512] = d2 * inv * w[t + 512] + b[t + 512];
}

// ---------------------------------------------------------------------------
// SGEMM: C[M,N] = A[M,K] @ B[K,N] (+bias[N]) (+GELU) (+res[M,N])
// 128x128x8 tiles, 256 threads, 8x8 microtile. All dims divisible.
// ---------------------------------------------------------------------------
template<int BIAS, int RES, int GELU>
__global__ void __launch_bounds__(256, 2) sgemm_k(
    const float* __restrict__ A, const float* __restrict__ Bm,
    const float* __restrict__ bias, const float* __restrict__ res,
    float* __restrict__ C, int M, int N, int K)
{
    __shared__ float As[8][128];
    __shared__ float Bs[8][128];
    int tid = threadIdx.x;
    int bn = blockIdx.x * 128;
    int bm = blockIdx.y * 128;
    int arow = tid >> 1;
    int acol = (tid & 1) << 2;
    int brow = tid >> 5;
    int bcol = (tid & 31) << 2;
    const float* Ap = A + (size_t)(bm + arow) * K + acol;
    const float* Bp = Bm + (size_t)brow * N + bn + bcol;
    int tx = tid & 15, ty = tid >> 4;
    float acc[8][8];
    #pragma unroll
    for (int i = 0; i < 8; i++)
        #pragma unroll
        for (int j = 0; j < 8; j++) acc[i][j] = 0.f;

    for (int k0 = 0; k0 < K; k0 += 8) {
        float4 a4 = *(const float4*)Ap;
        float4 b4 = *(const float4*)Bp;
        Ap += 8;
        Bp += (size_t)8 * N;
        __syncthreads();
        As[acol + 0][arow] = a4.x;
        As[acol + 1][arow] = a4.y;
        As[acol + 2][arow] = a4.z;
        As[acol + 3][arow] = a4.w;
        *(float4*)&Bs[brow][bcol] = b4;
        __syncthreads();
        #pragma unroll
        for (int kk = 0; kk < 8; kk++) {
            float ar[8], br[8];
            *(float4*)&ar[0] = *(const float4*)&As[kk][ty * 8];
            *(float4*)&ar[4] = *(const float4*)&As[kk][ty * 8 + 4];
            *(float4*)&br[0] = *(const float4*)&Bs[kk][tx * 8];
            *(float4*)&br[4] = *(const float4*)&Bs[kk][tx * 8 + 4];
            #pragma unroll
            for (int i = 0; i < 8; i++)
                #pragma unroll
                for (int j = 0; j < 8; j++)
                    acc[i][j] = fmaf(ar[i], br[j], acc[i][j]);
        }
    }
    #pragma unroll
    for (int i = 0; i < 8; i++) {
        int row = bm + ty * 8 + i;
        #pragma unroll
        for (int j = 0; j < 8; j++) {
            int col = bn + tx * 8 + j;
            float v = acc[i][j];
            if (BIAS) v += bias[col];
            if (GELU) v = 0.5f * v * (1.f + erff(v * 0.70710678118654752f));
            if (RES)  v += res[(size_t)row * N + col];
            C[(size_t)row * N + col] = v;
        }
    }
}

// ---------------------------------------------------------------------------
// Fused attention: one block per (b, h). Q,K,V staged in smem (stride 68
// floats -> conflict-free float4). Warp-per-row softmax + PV.
// Writes attention out in (b, n, h*64+d) layout. Row-0 probabilities go to
// per-head cls buffer (deterministic reduction later).
// ---------------------------------------------------------------------------
#define ATT_STRIDE 68
#define ATT_SMEM ((3 * SEQ * ATT_STRIDE + 8 * 200) * 4)

__global__ void attn_kernel(const float* __restrict__ qkv,
                            float* __restrict__ out,
                            float* __restrict__ clsh) {
    extern __shared__ float sm[];
    float* Qs = sm;
    float* Ks = Qs + SEQ * ATT_STRIDE;
    float* Vs = Ks + SEQ * ATT_STRIDE;
    float* Ps = Vs + SEQ * ATT_STRIDE;   // 8 warps x 200

    int bh = blockIdx.x;
    int b = bh / NHEAD, h = bh % NHEAD;
    const float* base = qkv + (size_t)b * SEQ * CH3 + h * HDIM;
    int tid = threadIdx.x;

    // stage Q (pre-scaled), K, V
    for (int idx = tid; idx < SEQ * (HDIM / 4); idx += 256) {
        int i = idx >> 4;
        int d4 = (idx & 15) << 2;
        const float* p = base + (size_t)i * CH3 + d4;
        float4 q4 = *(const float4*)(p);
        float4 k4 = *(const float4*)(p + CHN);
        float4 v4 = *(const float4*)(p + 2 * CHN);
        q4.x *= 0.125f; q4.y *= 0.125f; q4.z *= 0.125f; q4.w *= 0.125f;
        *(float4*)&Qs[i * ATT_STRIDE + d4] = q4;
        *(float4*)&Ks[i * ATT_STRIDE + d4] = k4;
        *(float4*)&Vs[i * ATT_STRIDE + d4] = v4;
    }
    __syncthreads();

    int w = tid >> 5, lane = tid & 31;
    float* Pw = Ps + w * 200;

    for (int i = w; i < SEQ; i += 8) {
        // scores for this row; lane handles j = lane + 32*t
        float s[7];
        #pragma unroll
        for (int t7 = 0; t7 < 7; t7++) s[t7] = 0.f;
        #pragma unroll
        for (int k = 0; k < HDIM; k += 4) {
            float4 q4 = *(const float4*)&Qs[i * ATT_STRIDE + k];
            #pragma unroll
            for (int t7 = 0; t7 < 7; t7++) {
                int j = lane + 32 * t7;
                if (j < SEQ) {
                    float4 k4 = *(const float4*)&Ks[j * ATT_STRIDE + k];
                    s[t7] = fmaf(q4.x, k4.x, fmaf(q4.y, k4.y,
                            fmaf(q4.z, k4.z, fmaf(q4.w, k4.w, s[t7]))));
                }
            }
        }
        float mx = -1e30f;
        #pragma unroll
        for (int t7 = 0; t7 < 7; t7++)
            if (lane + 32 * t7 < SEQ) mx = fmaxf(mx, s[t7]);
        #pragma unroll
        for (int o = 16; o; o >>= 1) mx = fmaxf(mx, __shfl_xor_sync(0xffffffffu, mx, o));
        float sum = 0.f, p[7];
        #pragma unroll
        for (int t7 = 0; t7 < 7; t7++) {
            if (lane + 32 * t7 < SEQ) { p[t7] = __expf(s[t7] - mx); sum += p[t7]; }
            else p[t7] = 0.f;
        }
        #pragma unroll
        for (int o = 16; o; o >>= 1) sum += __shfl_xor_sync(0xffffffffu, sum, o);
        float inv = 1.f / sum;
        #pragma unroll
        for (int t7 = 0; t7 < 7; t7++) {
            int j = lane + 32 * t7;
            if (j < SEQ) Pw[j] = p[t7] * inv;
        }
        __syncwarp();
        if (i == 0) {  // cls row: per-head probs for token scoring
            #pragma unroll
            for (int t7 = 0; t7 < 7; t7++) {
                int j = lane + 32 * t7;
                if (j >= 1 && j < SEQ)
                    clsh[(size_t)(b * NHEAD + h) * NM1 + (j - 1)] = p[t7] * inv;
            }
        }
        // PV: lane produces output cols lane, lane+32
        float o0 = 0.f, o1 = 0.f;
        for (int j4 = 0; j4 < 196; j4 += 4) {
            float4 p4 = *(const float4*)&Pw[j4];
            o0 = fmaf(p4.x, Vs[(j4 + 0) * ATT_STRIDE + lane], o0);
            o1 = fmaf(p4.x, Vs[(j4 + 0) * ATT_STRIDE + lane + 32], o1);
            o0 = fmaf(p4.y, Vs[(j4 + 1) * ATT_STRIDE + lane], o0);
            o1 = fmaf(p4.y, Vs[(j4 + 1) * ATT_STRIDE + lane + 32], o1);
            o0 = fmaf(p4.z, Vs[(j4 + 2) * ATT_STRIDE + lane], o0);
            o1 = fmaf(p4.z, Vs[(j4 + 2) * ATT_STRIDE + lane + 32], o1);
            o0 = fmaf(p4.w, Vs[(j4 + 3) * ATT_STRIDE + lane], o0);
            o1 = fmaf(p4.w, Vs[(j4 + 3) * ATT_STRIDE + lane + 32], o1);
        }
        float pl = Pw[196];
        o0 = fmaf(pl, Vs[196 * ATT_STRIDE + lane], o0);
        o1 = fmaf(pl, Vs[196 * ATT_STRIDE + lane + 32], o1);
        float* op = out + ((size_t)b * SEQ + i) * CHN + h * HDIM;
        op[lane] = o0;
        op[lane + 32] = o1;
        __syncwarp();
    }
}

// fixed-order head reduction -> deterministic cls_attn
__global__ void cls_reduce(const float* __restrict__ clsh, float* __restrict__ cls) {
    int b = blockIdx.x;
    for (int j = threadIdx.x; j < NM1; j += blockDim.x) {
        float s = 0.f;
        #pragma unroll
        for (int h = 0; h < NHEAD; h++)
            s += clsh[(size_t)(b * NHEAD + h) * NM1 + j];
        cls[b * NM1 + j] = s * (1.f / NHEAD);
    }
}

// stable top-k (value desc, index asc) by O(n^2) ranking; sorted complement
__global__ void topk_kernel(const float* __restrict__ cls,
                            int* __restrict__ idx, int* __restrict__ cmp) {
    __shared__ float v[NM1];
    __shared__ int taken[NM1];
    int b = blockIdx.x, t = threadIdx.x;
    if (t < NM1) v[t] = cls[b * NM1 + t];
    __syncthreads();
    if (t < NM1) {
        float mv = v[t];
        int rank = 0;
        for (int j = 0; j < NM1; j++) {
            float vj = v[j];
            rank += (vj > mv) || (vj == mv && j < t);
        }
        taken[t] = (rank < LEFT);
        if (rank < LEFT) idx[b * LEFT + rank] = t;
    }
    __syncthreads();
    if (t == 0) {
        int c = 0;
        for (int i = 0; i < NM1; i++)
            if (!taken[i]) cmp[b * NCOMP + c++] = i;
    }
}

// norms of the kept (top-k) token rows of x1
__global__ void norm_kernel(const float* __restrict__ x1, const int* __restrict__ idx,
                            float* __restrict__ xon) {
    int b = blockIdx.x;
    int w = threadIdx.x >> 5, lane = threadIdx.x & 31;
    for (int l = w; l < LEFT; l += 8) {
        const float* row = x1 + ((size_t)b * SEQ + 1 + idx[b * LEFT + l]) * CHN;
        float s = 0.f;
        for (int c = lane * 4; c < CHN; c += 128) {
            float4 r = *(const float4*)(row + c);
            s = fmaf(r.x, r.x, fmaf(r.y, r.y, fmaf(r.z, r.z, fmaf(r.w, r.w, s))));
        }
        #pragma unroll
        for (int o = 16; o; o >>= 1) s += __shfl_xor_sync(0xffffffffu, s, o);
        if (lane == 0) xon[b * LEFT + l] = sqrtf(s);
    }
}

// for each pruned token m: argmax_l of cos-similarity with kept tokens
__global__ void dist_kernel(const float* __restrict__ x1, const int* __restrict__ idx,
                            const int* __restrict__ cmp, const float* __restrict__ xon,
                            int* __restrict__ node) {
    __shared__ float nt[CHN];
    __shared__ float bv[8];
    __shared__ int bl[8];
    int m = blockIdx.x, b = blockIdx.y;
    int tid = threadIdx.x;
    const float* ntrow = x1 + ((size_t)b * SEQ + 1 + cmp[b * NCOMP + m]) * CHN;
    for (int c = tid; c < CHN; c += 256) nt[c] = ntrow[c];
    __syncthreads();
    int w = tid >> 5, lane = tid & 31;
    float bestv = -1e30f;
    int bestl = 0;
    for (int l = w; l < LEFT; l += 8) {
        const float* row = x1 + ((size_t)b * SEQ + 1 + idx[b * LEFT + l]) * CHN;
        float s = 0.f;
        for (int c = lane * 4; c < CHN; c += 128) {
            float4 a = *(const float4*)&nt[c];
            float4 r = *(const float4*)(row + c);
            s = fmaf(a.x, r.x, fmaf(a.y, r.y, fmaf(a.z, r.z, fmaf(a.w, r.w, s))));
        }
        #pragma unroll
        for (int o = 16; o; o >>= 1) s += __shfl_xor_sync(0xffffffffu, s, o);
        if (lane == 0) {
            float val = s / xon[b * LEFT + l];
            if (val > bestv) { bestv = val; bestl = l; }   // strict > keeps lowest l
        }
    }
    if (lane == 0) { bv[w] = bestv; bl[w] = bestl; }
    __syncthreads();
    if (tid == 0) {
        float best = bv[0]; int bi = bl[0];
        for (int ww = 1; ww < 8; ww++) {
            if (bv[ww] > best || (bv[ww] == best && bl[ww] < bi)) { best = bv[ww]; bi = bl[ww]; }
        }
        node[b * NCOMP + m] = bi;
    }
}

// build x_cat: cls row + attention-weighted kept tokens with merged pruned
// tokens, divided by accumulated attention. Deterministic (column ownership).
__global__ void fuse_kernel(const float* __restrict__ x1, const float* __restrict__ cls,
                            const int* __restrict__ idx, const int* __restrict__ cmp,
                            const int* __restrict__ node, float* __restrict__ xcat) {
    __shared__ float ta[LEFT];
    int b = blockIdx.x, t = threadIdx.x;
    if (t < LEFT) ta[t] = cls[b * NM1 + idx[b * LEFT + t]];
    for (int c = t; c < CHN; c += 256)
        xcat[(size_t)b * SEQ2 * CHN + c] = x1[(size_t)b * SEQ * CHN + c];
    // phase A: weighted kept tokens
    for (int rc = t; rc < LEFT * CHN; rc += 256) {
        int r = rc / CHN, c = rc % CHN;
        int src = idx[b * LEFT + r];
        xcat[((size_t)b * SEQ2 + 1 + r) * CHN + c] =
            x1[((size_t)b * SEQ + 1 + src) * CHN + c] * cls[b * NM1 + src];
    }
    __syncthreads();
    // phase B: merge pruned tokens (thread t owns cols c == t mod 256)
    for (int m = 0; m < NCOMP; m++) {
        int ni = node[b * NCOMP + m];
        int cm = cmp[b * NCOMP + m];
        float a = cls[b * NM1 + cm];
        for (int c = t; c < CHN; c += 256)
            xcat[((size_t)b * SEQ2 + 1 + ni) * CHN + c] +=
                x1[((size_t)b * SEQ + 1 + cm) * CHN + c] * a;
        if (t == 0) ta[ni] += a;
    }
    __syncthreads();
    // phase C: normalize by accumulated attention
    for (int rc = t; rc < LEFT * CHN; rc += 256) {
        int r = rc / CHN, c = rc % CHN;
        xcat[((size_t)b * SEQ2 + 1 + r) * CHN + c] /= ta[r];
    }
}

// ---------------------------------------------------------------------------
extern "C" void kernel_launch(void* const* d_in, const int* in_sizes, int n_in,
                              void* d_out, int out_size) {
    const float* x     = (const float*)d_in[0];
    const float* n1w   = (const float*)d_in[1];
    const float* n1b   = (const float*)d_in[2];
    const float* qkvw  = (const float*)d_in[3];
    const float* projw = (const float*)d_in[4];
    const float* projb = (const float*)d_in[5];
    const float* n2w   = (const float*)d_in[6];
    const float* n2b   = (const float*)d_in[7];
    const float* fc1w  = (const float*)d_in[8];
    const float* fc1b  = (const float*)d_in[9];
    const float* fc2w  = (const float*)d_in[10];
    const float* fc2b  = (const float*)d_in[11];

    float *xn, *qkv, *ao, *x1, *clsh, *cls, *xon, *xcat, *xn2, *hmid;
    int *idx, *cmp, *node;
    cudaGetSymbolAddress((void**)&xn,   g_xn);
    cudaGetSymbolAddress((void**)&qkv,  g_qkv);
    cudaGetSymbolAddress((void**)&ao,   g_ao);
    cudaGetSymbolAddress((void**)&x1,   g_x1);
    cudaGetSymbolAddress((void**)&clsh, g_clsh);
    cudaGetSymbolAddress((void**)&cls,  g_cls);
    cudaGetSymbolAddress((void**)&idx,  g_idx);
    cudaGetSymbolAddress((void**)&cmp,  g_cmp);
    cudaGetSymbolAddress((void**)&xon,  g_xon);
    cudaGetSymbolAddress((void**)&node, g_node);
    cudaGetSymbolAddress((void**)&xcat, g_xcat);
    cudaGetSymbolAddress((void**)&xn2,  g_xn2);
    cudaGetSymbolAddress((void**)&hmid, g_hmid);

    cudaFuncSetAttribute(attn_kernel, cudaFuncAttributeMaxDynamicSharedMemorySize, ATT_SMEM);

    const int M1 = BBATCH * SEQ;   // 25216
    const int M2 = BBATCH * SEQ2;  // 17792

    // 1. LN1
    ln_kernel<<<M1, 256>>>(x, n1w, n1b, xn);
    // 2. QKV
    sgemm_k<0,0,0><<<dim3(CH3/128, M1/128), 256>>>(xn, qkvw, nullptr, nullptr, qkv, M1, CH3, CHN);
    // 3. fused attention (+ per-head cls probs)
    attn_kernel<<<BBATCH*NHEAD, 256, ATT_SMEM>>>(qkv, ao, clsh);
    // 4. cls_attn = mean over heads (fixed order)
    cls_reduce<<<BBATCH, 256>>>(clsh, cls);
    // 5. proj + bias + residual(x)
    sgemm_k<1,1,0><<<dim3(CHN/128, M1/128), 256>>>(ao, projw, projb, x, x1, M1, CHN, CHN);
    // 6. token selection + merge
    topk_kernel<<<BBATCH, 256>>>(cls, idx, cmp);
    norm_kernel<<<BBATCH, 256>>>(x1, idx, xon);
    dist_kernel<<<dim3(NCOMP, BBATCH), 256>>>(x1, idx, cmp, xon, node);
    fuse_kernel<<<BBATCH, 256>>>(x1, cls, idx, cmp, node, xcat);
    // 7. LN2
    ln_kernel<<<M2, 256>>>(xcat, n2w, n2b, xn2);
    // 8. FC1 + bias + exact GELU
    sgemm_k<1,0,1><<<dim3(HID/128, M2/128), 256>>>(xn2, fc1w, fc1b, nullptr, hmid, M2, HID, CHN);
    // 9. FC2 + bias + residual(xcat) -> output
    sgemm_k<1,1,0><<<dim3(CHN/128, M2/128), 256>>>(hmid, fc2w, fc2b, xcat, (float*)d_out, M2, CHN, HID);
}